// round 1
// baseline (speedup 1.0000x reference)
#include <cuda_runtime.h>
#include <cstdint>
#include <cstddef>

#define S_LEN 512
#define B_TOT 512

// Scratch for precomputed input projections of cell 0: [S][B][128]
__device__ float g_xin0[(size_t)S_LEN * B_TOT * 128];
__device__ float g_xg0[(size_t)S_LEN * B_TOT * 128];

// ---------------- packed fp32x2 helpers (SASS FFMA2 path, PTX-only) ----------------
__device__ __forceinline__ unsigned long long ffma2(unsigned long long a,
                                                    unsigned long long b,
                                                    unsigned long long c) {
    unsigned long long d;
    asm("fma.rn.f32x2 %0, %1, %2, %3;" : "=l"(d) : "l"(a), "l"(b), "l"(c));
    return d;
}
__device__ __forceinline__ float redu2(unsigned long long v) {
    float lo, hi;
    asm("mov.b64 {%0, %1}, %2;" : "=f"(lo), "=f"(hi) : "l"(v));
    return lo + hi;
}

__device__ __forceinline__ float sigm(float x) {
    return __fdividef(1.0f, 1.0f + __expf(-x));
}
// tanh via exp; stable for large |x| (exp->inf => t->1); abs err ~1e-7
__device__ __forceinline__ float fast_tanh(float x) {
    float ax = fabsf(x);
    float e = __expf(ax + ax);
    float t = 1.0f - __fdividef(2.0f, e + 1.0f);
    return copysignf(t, x);
}

// rr[b] = dot(Wrow[0:128], hh[b*128 : b*128+128]) for b = 0..3
// Wrow: global (L1-cached), hh: shared (broadcast reads)
__device__ __forceinline__ void matvec4(const float* __restrict__ Wrow,
                                        const float* __restrict__ hh,
                                        float rr[4]) {
    const ulonglong2* wp = reinterpret_cast<const ulonglong2*>(Wrow);
    const ulonglong2* h0 = reinterpret_cast<const ulonglong2*>(hh);
    const ulonglong2* h1 = reinterpret_cast<const ulonglong2*>(hh + 128);
    const ulonglong2* h2 = reinterpret_cast<const ulonglong2*>(hh + 256);
    const ulonglong2* h3 = reinterpret_cast<const ulonglong2*>(hh + 384);
    unsigned long long a0 = 0ull, a1 = 0ull, a2 = 0ull, a3 = 0ull;
#pragma unroll 8
    for (int kc = 0; kc < 32; ++kc) {
        ulonglong2 w = __ldg(wp + kc);
        ulonglong2 x0 = h0[kc];
        ulonglong2 x1 = h1[kc];
        ulonglong2 x2 = h2[kc];
        ulonglong2 x3 = h3[kc];
        a0 = ffma2(w.x, x0.x, a0);
        a1 = ffma2(w.x, x1.x, a1);
        a2 = ffma2(w.x, x2.x, a2);
        a3 = ffma2(w.x, x3.x, a3);
        a0 = ffma2(w.y, x0.y, a0);
        a1 = ffma2(w.y, x1.y, a1);
        a2 = ffma2(w.y, x2.y, a2);
        a3 = ffma2(w.y, x3.y, a3);
    }
    rr[0] = redu2(a0);
    rr[1] = redu2(a1);
    rr[2] = redu2(a2);
    rr[3] = redu2(a3);
}

// One LTC cell: RK4 over  dh/dt = -h/tau + xin + sigmoid(tanh(xg + h@Wgh^T)) * (h@Wrec^T)
// On entry hh_s holds the current h for all 4 local batches; on exit hh_s holds the
// updated h (= tanh(h + (k1+2k2+2k3+k4)/6)) and hreg[] is updated for this thread's
// two owned batches.
__device__ __forceinline__ void cell_rk4(const float* __restrict__ Wsel, float itau,
                                         float* hreg, const float* xin, const float* xg,
                                         float* hh_s, float* res_s, int j, int half) {
    float ka[2] = {0.f, 0.f};
    float hhr[2] = {hreg[0], hreg[1]};
#pragma unroll
    for (int sub = 0; sub < 4; ++sub) {
        float rr[4];
        matvec4(Wsel, hh_s, rr);
        float* dst = res_s + half * 512;
        dst[0 * 128 + j] = rr[0];
        dst[1 * 128 + j] = rr[1];
        dst[2 * 128 + j] = rr[2];
        dst[3 * 128 + j] = rr[3];
        __syncthreads();
        const float kwv = (sub == 0 || sub == 3) ? 1.0f : 2.0f;
        const float cnv = (sub < 2) ? 0.5f : 1.0f;
#pragma unroll
        for (int bb = 0; bb < 2; ++bb) {
            int b = half * 2 + bb;
            float g = res_s[b * 128 + j] + xg[bb];               // gate matmul (half 0)
            float gate = sigm(fast_tanh(g));
            float rv = res_s[512 + b * 128 + j];                 // recurrent matmul (half 1)
            float kv = fmaf(gate, rv, fmaf(-hhr[bb], itau, xin[bb]));
            ka[bb] = fmaf(kwv, kv, ka[bb]);
            float nh;
            if (sub < 3)
                nh = fmaf(cnv, kv, hreg[bb]);
            else
                nh = fast_tanh(fmaf(ka[bb], 0.16666667f, hreg[bb]));
            hhr[bb] = nh;
            hh_s[b * 128 + j] = nh;
        }
        __syncthreads();
    }
    hreg[0] = hhr[0];
    hreg[1] = hhr[1];
}

// ---------------- Kernel 1: precompute x-projections for cell 0 ----------------
// xin0[s][b][j] = sum_i X[b][s][i] * Win0[j][i]
// xg0 [s][b][j] = sum_i X[b][s][i] * Wg0[j][i] + bg0[j]   (first 96 cols of Wg0)
__global__ void __launch_bounds__(256) ltc_precompute(const float* __restrict__ seq,
                                                      const float* __restrict__ ctx,
                                                      const float* __restrict__ Win0,
                                                      const float* __restrict__ Wg0,
                                                      const float* __restrict__ bg0) {
    __shared__ __align__(16) float Xs[8 * 96];
    const int s = blockIdx.x;
    const int b0 = blockIdx.y * 8;
    const int tid = threadIdx.x;
    for (int idx = tid; idx < 8 * 96; idx += 256) {
        int b = idx / 96;
        int i = idx - b * 96;
        float v = (i < 64) ? seq[((size_t)(b0 + b) * S_LEN + s) * 64 + i]
                           : ctx[(size_t)(b0 + b) * 32 + (i - 64)];
        Xs[idx] = v;
    }
    __syncthreads();
    const int j = tid & 127;
    const int m = tid >> 7;
    const float* Wrow = m ? (Wg0 + j * 224) : (Win0 + j * 96);
    const ulonglong2* wp = reinterpret_cast<const ulonglong2*>(Wrow);
    unsigned long long acc[8];
#pragma unroll
    for (int b = 0; b < 8; ++b) acc[b] = 0ull;
#pragma unroll 4
    for (int kc = 0; kc < 24; ++kc) {
        ulonglong2 w = __ldg(wp + kc);
#pragma unroll
        for (int b = 0; b < 8; ++b) {
            ulonglong2 x = reinterpret_cast<const ulonglong2*>(Xs + b * 96)[kc];
            acc[b] = ffma2(w.x, x.x, acc[b]);
            acc[b] = ffma2(w.y, x.y, acc[b]);
        }
    }
    const float bias = m ? bg0[j] : 0.0f;
    float* dst = (m ? g_xg0 : g_xin0) + ((size_t)s * B_TOT + b0) * 128 + j;
#pragma unroll
    for (int b = 0; b < 8; ++b) dst[(size_t)b * 128] = redu2(acc[b]) + bias;
}

// ---------------- Kernel 2: persistent recurrence ----------------
// Grid 128 CTAs x 256 threads. Each CTA owns 4 batch elements for the full sequence.
// Thread (j = tid&127, half = tid>>7): half 0 computes the gate matmul rows, half 1
// the recurrent matmul rows; elementwise work is split 2 batches per half.
__global__ void __launch_bounds__(256, 1)
ltc_recurrent(const float* __restrict__ tau0, const float* __restrict__ Wrec0,
              const float* __restrict__ Wg0, const float* __restrict__ tau1,
              const float* __restrict__ Win1, const float* __restrict__ Wrec1,
              const float* __restrict__ Wg1, const float* __restrict__ bg1,
              const float* __restrict__ W1, const float* __restrict__ b1,
              const float* __restrict__ W2, const float* __restrict__ b2,
              float* __restrict__ out) {
    __shared__ __align__(16) float hh_s[4 * 128];
    __shared__ __align__(16) float res_s[2 * 4 * 128];
    const int tid = threadIdx.x;
    const int j = tid & 127;
    const int half = tid >> 7;
    const int b0 = blockIdx.x * 4;

    // tau = softplus(tau_p) + 1 ; itau = 1/tau
    const float it0 = __fdividef(1.0f, log1pf(__expf(tau0[j])) + 1.0f);
    const float it1 = __fdividef(1.0f, log1pf(__expf(tau1[j])) + 1.0f);
    const float bg1j = bg1[j];

    // weight row pointers for this thread (all 16B aligned)
    const float* Wc0 = half ? (Wrec0 + j * 128) : (Wg0 + j * 224 + 96);
    const float* Wp  = half ? (Wg1 + j * 256)   : (Win1 + j * 128);
    const float* Wc1 = half ? (Wrec1 + j * 128) : (Wg1 + j * 256 + 128);

    float h0r[2] = {0.f, 0.f}, h1r[2] = {0.f, 0.f};
    hh_s[(half * 2 + 0) * 128 + j] = 0.f;
    hh_s[(half * 2 + 1) * 128 + j] = 0.f;
    __syncthreads();

    for (int s = 0; s < S_LEN; ++s) {
        float xin[2], xg[2];
        {
            size_t base = ((size_t)s * B_TOT + b0 + half * 2) * 128 + j;
            xin[0] = g_xin0[base];
            xin[1] = g_xin0[base + 128];
            xg[0] = g_xg0[base];
            xg[1] = g_xg0[base + 128];
        }
        // ---- cell 0 (hh_s currently holds h0) ----
        cell_rk4(Wc0, it0, h0r, xin, xg, hh_s, res_s, j, half);

        // ---- cell 1 input projections from h0_new (in hh_s) ----
        {
            float rr[4];
            matvec4(Wp, hh_s, rr);
            float* dst = res_s + half * 512;
            dst[0 * 128 + j] = rr[0];
            dst[1 * 128 + j] = rr[1];
            dst[2 * 128 + j] = rr[2];
            dst[3 * 128 + j] = rr[3];
            __syncthreads();
            int bA = half * 2, bB = bA + 1;
            xin[0] = res_s[bA * 128 + j];
            xin[1] = res_s[bB * 128 + j];
            xg[0] = res_s[512 + bA * 128 + j] + bg1j;
            xg[1] = res_s[512 + bB * 128 + j] + bg1j;
            hh_s[bA * 128 + j] = h1r[0];
            hh_s[bB * 128 + j] = h1r[1];
            __syncthreads();
        }
        // ---- cell 1 ----
        cell_rk4(Wc1, it1, h1r, xin, xg, hh_s, res_s, j, half);

        // restore hh_s = h0 for the next step
        hh_s[(half * 2 + 0) * 128 + j] = h0r[0];
        hh_s[(half * 2 + 1) * 128 + j] = h0r[1];
        __syncthreads();
    }

    // ---- classifier: sigmoid(relu(h1 @ W1^T + b1) @ W2^T + b2) ----
    hh_s[(half * 2 + 0) * 128 + j] = h1r[0];
    hh_s[(half * 2 + 1) * 128 + j] = h1r[1];
    __syncthreads();
    const int warp = tid >> 5, lane = tid & 31;
    if (warp < 4) {
        const int b = warp;
        float a0 = b1[lane], a1 = b1[lane + 32];
        const float* hv = hh_s + b * 128;
        const float* w0 = W1 + lane * 128;
        const float* w1 = W1 + (lane + 32) * 128;
#pragma unroll 8
        for (int k = 0; k < 128; ++k) {
            float h = hv[k];
            a0 = fmaf(h, w0[k], a0);
            a1 = fmaf(h, w1[k], a1);
        }
        a0 = fmaxf(a0, 0.f);
        a1 = fmaxf(a1, 0.f);
        float p = a0 * __ldg(W2 + lane) + a1 * __ldg(W2 + lane + 32);
#pragma unroll
        for (int off = 16; off; off >>= 1) p += __shfl_xor_sync(0xffffffffu, p, off);
        if (lane == 0) out[b0 + b] = sigm(p + b2[0]);
    }
}

extern "C" void kernel_launch(void* const* d_in, const int* in_sizes, int n_in,
                              void* d_out, int out_size) {
    const float* seq   = (const float*)d_in[0];
    const float* ctx   = (const float*)d_in[1];
    const float* tau0  = (const float*)d_in[2];
    const float* Win0  = (const float*)d_in[3];
    const float* Wrec0 = (const float*)d_in[4];
    const float* Wg0   = (const float*)d_in[5];
    const float* bg0   = (const float*)d_in[6];
    const float* tau1  = (const float*)d_in[7];
    const float* Win1  = (const float*)d_in[8];
    const float* Wrec1 = (const float*)d_in[9];
    const float* Wg1   = (const float*)d_in[10];
    const float* bg1   = (const float*)d_in[11];
    const float* W1    = (const float*)d_in[12];
    const float* b1    = (const float*)d_in[13];
    const float* W2    = (const float*)d_in[14];
    const float* b2    = (const float*)d_in[15];
    float* out = (float*)d_out;

    dim3 g1(S_LEN, B_TOT / 8);
    ltc_precompute<<<g1, 256>>>(seq, ctx, Win0, Wg0, bg0);
    ltc_recurrent<<<128, 256>>>(tau0, Wrec0, Wg0, tau1, Win1, Wrec1, Wg1, bg1,
                                W1, b1, W2, b2, out);
}

// round 2
// speedup vs baseline: 2.7810x; 2.7810x over previous
#include <cuda_runtime.h>
#include <cstdint>
#include <cstddef>

#define S_LEN 512
#define B_TOT 512

// Scratch for precomputed input projections of cell 0: [S][B][128]
__device__ float g_xin0[(size_t)S_LEN * B_TOT * 128];
__device__ float g_xg0[(size_t)S_LEN * B_TOT * 128];

// Transposed (k-quad major) weights: Wq[kq][j][4], i.e. element (j,k) at
// (k/4)*512 + j*4 + (k%4). Matrices: 0:Wg0h 1:Wrec0 2:Win1 3:Wg1x 4:Wg1h 5:Wrec1
__device__ float g_Wq[6][128 * 128];
// Same layout for the precompute matrices (96 cols): 0:Win0 1:Wg0x
__device__ float g_WqP[2][96 * 128];

// ---------------- packed fp32x2 helpers (SASS FFMA2 path, PTX-only) ----------------
__device__ __forceinline__ unsigned long long ffma2(unsigned long long a,
                                                    unsigned long long b,
                                                    unsigned long long c) {
    unsigned long long d;
    asm("fma.rn.f32x2 %0, %1, %2, %3;" : "=l"(d) : "l"(a), "l"(b), "l"(c));
    return d;
}
__device__ __forceinline__ float redu2(unsigned long long v) {
    float lo, hi;
    asm("mov.b64 {%0, %1}, %2;" : "=f"(lo), "=f"(hi) : "l"(v));
    return lo + hi;
}

__device__ __forceinline__ float sigm(float x) {
    return __fdividef(1.0f, 1.0f + __expf(-x));
}
// tanh via exp; stable for large |x|; abs err ~1e-7
__device__ __forceinline__ float fast_tanh(float x) {
    float ax = fabsf(x);
    float e = __expf(ax + ax);
    float t = 1.0f - __fdividef(2.0f, e + 1.0f);
    return copysignf(t, x);
}

// ---------------- weight layout prep (runs once per launch, ~µs) ----------------
__global__ void __launch_bounds__(256) prep_weights(
    const float* __restrict__ Win0, const float* __restrict__ Wg0,
    const float* __restrict__ Wrec0, const float* __restrict__ Win1,
    const float* __restrict__ Wrec1, const float* __restrict__ Wg1) {
    int idx = blockIdx.x * blockDim.x + threadIdx.x;
    if (idx < 6 * 16384) {
        int mat = idx >> 14;
        int e = idx & 16383;
        int j = e >> 7;
        int k = e & 127;
        float v;
        switch (mat) {
            case 0: v = Wg0[j * 224 + 96 + k]; break;
            case 1: v = Wrec0[j * 128 + k]; break;
            case 2: v = Win1[j * 128 + k]; break;
            case 3: v = Wg1[j * 256 + k]; break;
            case 4: v = Wg1[j * 256 + 128 + k]; break;
            default: v = Wrec1[j * 128 + k]; break;
        }
        g_Wq[mat][(k >> 2) * 512 + j * 4 + (k & 3)] = v;
    } else if (idx < 6 * 16384 + 2 * 12288) {
        int e = idx - 6 * 16384;
        int m = e / 12288;
        int r = e % 12288;
        int j = r / 96;
        int k = r % 96;
        float v = m ? Wg0[j * 224 + k] : Win0[j * 96 + k];
        g_WqP[m][(k >> 2) * 512 + j * 4 + (k & 3)] = v;
    }
}

// rr[b] = dot(W row j, hh[b]) with W in k-quad-major layout (Wq = base + j*4).
// Coalesced: a warp's lanes read 512B contiguous per LDG.128 (4 lines vs ~32).
__device__ __forceinline__ void matvec4(const float* __restrict__ Wq,
                                        const float* __restrict__ hh,
                                        float rr[4]) {
    const ulonglong2* h0 = reinterpret_cast<const ulonglong2*>(hh);
    const ulonglong2* h1 = reinterpret_cast<const ulonglong2*>(hh + 128);
    const ulonglong2* h2 = reinterpret_cast<const ulonglong2*>(hh + 256);
    const ulonglong2* h3 = reinterpret_cast<const ulonglong2*>(hh + 384);
    unsigned long long a0 = 0ull, a1 = 0ull, a2 = 0ull, a3 = 0ull;
#pragma unroll 8
    for (int kq = 0; kq < 32; ++kq) {
        ulonglong2 w = __ldg(reinterpret_cast<const ulonglong2*>(Wq + (size_t)kq * 512));
        ulonglong2 x0 = h0[kq];
        ulonglong2 x1 = h1[kq];
        ulonglong2 x2 = h2[kq];
        ulonglong2 x3 = h3[kq];
        a0 = ffma2(w.x, x0.x, a0);
        a1 = ffma2(w.x, x1.x, a1);
        a2 = ffma2(w.x, x2.x, a2);
        a3 = ffma2(w.x, x3.x, a3);
        a0 = ffma2(w.y, x0.y, a0);
        a1 = ffma2(w.y, x1.y, a1);
        a2 = ffma2(w.y, x2.y, a2);
        a3 = ffma2(w.y, x3.y, a3);
    }
    rr[0] = redu2(a0);
    rr[1] = redu2(a1);
    rr[2] = redu2(a2);
    rr[3] = redu2(a3);
}

// One LTC cell RK4 step (see round-1 comments). hh_s in/out holds h for 4 batches.
__device__ __forceinline__ void cell_rk4(const float* __restrict__ Wsel, float itau,
                                         float* hreg, const float* xin, const float* xg,
                                         float* hh_s, float* res_s, int j, int half) {
    float ka[2] = {0.f, 0.f};
    float hhr[2] = {hreg[0], hreg[1]};
#pragma unroll
    for (int sub = 0; sub < 4; ++sub) {
        float rr[4];
        matvec4(Wsel, hh_s, rr);
        float* dst = res_s + half * 512;
        dst[0 * 128 + j] = rr[0];
        dst[1 * 128 + j] = rr[1];
        dst[2 * 128 + j] = rr[2];
        dst[3 * 128 + j] = rr[3];
        __syncthreads();
        const float kwv = (sub == 0 || sub == 3) ? 1.0f : 2.0f;
        const float cnv = (sub < 2) ? 0.5f : 1.0f;
#pragma unroll
        for (int bb = 0; bb < 2; ++bb) {
            int b = half * 2 + bb;
            float g = res_s[b * 128 + j] + xg[bb];   // gate matmul result (half-0 rows)
            float gate = sigm(fast_tanh(g));
            float rv = res_s[512 + b * 128 + j];     // recurrent matmul result (half-1 rows)
            float kv = fmaf(gate, rv, fmaf(-hhr[bb], itau, xin[bb]));
            ka[bb] = fmaf(kwv, kv, ka[bb]);
            float nh;
            if (sub < 3)
                nh = fmaf(cnv, kv, hreg[bb]);
            else
                nh = fast_tanh(fmaf(ka[bb], 0.16666667f, hreg[bb]));
            hhr[bb] = nh;
            hh_s[b * 128 + j] = nh;
        }
        __syncthreads();
    }
    hreg[0] = hhr[0];
    hreg[1] = hhr[1];
}

// ---------------- Kernel 1: precompute x-projections for cell 0 ----------------
__global__ void __launch_bounds__(256) ltc_precompute(const float* __restrict__ seq,
                                                      const float* __restrict__ ctx,
                                                      const float* __restrict__ bg0) {
    __shared__ __align__(16) float Xs[8 * 96];
    const int s = blockIdx.x;
    const int b0 = blockIdx.y * 8;
    const int tid = threadIdx.x;
    for (int idx = tid; idx < 8 * 96; idx += 256) {
        int b = idx / 96;
        int i = idx - b * 96;
        float v = (i < 64) ? seq[((size_t)(b0 + b) * S_LEN + s) * 64 + i]
                           : ctx[(size_t)(b0 + b) * 32 + (i - 64)];
        Xs[idx] = v;
    }
    __syncthreads();
    const int j = tid & 127;
    const int m = tid >> 7;
    const float* Wq = g_WqP[m] + j * 4;
    unsigned long long acc[8];
#pragma unroll
    for (int b = 0; b < 8; ++b) acc[b] = 0ull;
#pragma unroll 4
    for (int kc = 0; kc < 24; ++kc) {
        ulonglong2 w = __ldg(reinterpret_cast<const ulonglong2*>(Wq + (size_t)kc * 512));
#pragma unroll
        for (int b = 0; b < 8; ++b) {
            ulonglong2 x = reinterpret_cast<const ulonglong2*>(Xs + b * 96)[kc];
            acc[b] = ffma2(w.x, x.x, acc[b]);
            acc[b] = ffma2(w.y, x.y, acc[b]);
        }
    }
    const float bias = m ? bg0[j] : 0.0f;
    float* dst = (m ? g_xg0 : g_xin0) + ((size_t)s * B_TOT + b0) * 128 + j;
#pragma unroll
    for (int b = 0; b < 8; ++b) dst[(size_t)b * 128] = redu2(acc[b]) + bias;
}

// ---------------- Kernel 2: persistent recurrence ----------------
__global__ void __launch_bounds__(256, 1)
ltc_recurrent(const float* __restrict__ tau0, const float* __restrict__ tau1,
              const float* __restrict__ bg1, const float* __restrict__ W1,
              const float* __restrict__ b1, const float* __restrict__ W2,
              const float* __restrict__ b2, float* __restrict__ out) {
    __shared__ __align__(16) float hh_s[4 * 128];
    __shared__ __align__(16) float res_s[2 * 4 * 128];
    const int tid = threadIdx.x;
    const int j = tid & 127;
    const int half = tid >> 7;
    const int b0 = blockIdx.x * 4;

    const float it0 = __fdividef(1.0f, log1pf(__expf(tau0[j])) + 1.0f);
    const float it1 = __fdividef(1.0f, log1pf(__expf(tau1[j])) + 1.0f);
    const float bg1j = bg1[j];

    // transposed weight bases for this thread's row j (half 0: gate, half 1: rec)
    const float* Wc0 = g_Wq[half ? 1 : 0] + j * 4;
    const float* Wp  = g_Wq[half ? 3 : 2] + j * 4;
    const float* Wc1 = g_Wq[half ? 5 : 4] + j * 4;

    float h0r[2] = {0.f, 0.f}, h1r[2] = {0.f, 0.f};
    hh_s[(half * 2 + 0) * 128 + j] = 0.f;
    hh_s[(half * 2 + 1) * 128 + j] = 0.f;
    __syncthreads();

    for (int s = 0; s < S_LEN; ++s) {
        float xin[2], xg[2];
        {
            size_t base = ((size_t)s * B_TOT + b0 + half * 2) * 128 + j;
            xin[0] = g_xin0[base];
            xin[1] = g_xin0[base + 128];
            xg[0] = g_xg0[base];
            xg[1] = g_xg0[base + 128];
        }
        // ---- cell 0 (hh_s currently holds h0) ----
        cell_rk4(Wc0, it0, h0r, xin, xg, hh_s, res_s, j, half);

        // ---- cell 1 input projections from h0_new ----
        {
            float rr[4];
            matvec4(Wp, hh_s, rr);
            float* dst = res_s + half * 512;
            dst[0 * 128 + j] = rr[0];
            dst[1 * 128 + j] = rr[1];
            dst[2 * 128 + j] = rr[2];
            dst[3 * 128 + j] = rr[3];
            __syncthreads();
            int bA = half * 2, bB = bA + 1;
            xin[0] = res_s[bA * 128 + j];
            xin[1] = res_s[bB * 128 + j];
            xg[0] = res_s[512 + bA * 128 + j] + bg1j;
            xg[1] = res_s[512 + bB * 128 + j] + bg1j;
            hh_s[bA * 128 + j] = h1r[0];
            hh_s[bB * 128 + j] = h1r[1];
            __syncthreads();
        }
        // ---- cell 1 ----
        cell_rk4(Wc1, it1, h1r, xin, xg, hh_s, res_s, j, half);

        // restore hh_s = h0 for the next step
        hh_s[(half * 2 + 0) * 128 + j] = h0r[0];
        hh_s[(half * 2 + 1) * 128 + j] = h0r[1];
        __syncthreads();
    }

    // ---- classifier: sigmoid(relu(h1 @ W1^T + b1) @ W2^T + b2) ----
    hh_s[(half * 2 + 0) * 128 + j] = h1r[0];
    hh_s[(half * 2 + 1) * 128 + j] = h1r[1];
    __syncthreads();
    const int warp = tid >> 5, lane = tid & 31;
    if (warp < 4) {
        const int b = warp;
        float a0 = b1[lane], a1 = b1[lane + 32];
        const float* hv = hh_s + b * 128;
        const float* w0 = W1 + lane * 128;
        const float* w1 = W1 + (lane + 32) * 128;
#pragma unroll 8
        for (int k = 0; k < 128; ++k) {
            float h = hv[k];
            a0 = fmaf(h, w0[k], a0);
            a1 = fmaf(h, w1[k], a1);
        }
        a0 = fmaxf(a0, 0.f);
        a1 = fmaxf(a1, 0.f);
        float p = a0 * __ldg(W2 + lane) + a1 * __ldg(W2 + lane + 32);
#pragma unroll
        for (int off = 16; off; off >>= 1) p += __shfl_xor_sync(0xffffffffu, p, off);
        if (lane == 0) out[b0 + b] = sigm(p + b2[0]);
    }
}

extern "C" void kernel_launch(void* const* d_in, const int* in_sizes, int n_in,
                              void* d_out, int out_size) {
    const float* seq   = (const float*)d_in[0];
    const float* ctx   = (const float*)d_in[1];
    const float* tau0  = (const float*)d_in[2];
    const float* Win0  = (const float*)d_in[3];
    const float* Wrec0 = (const float*)d_in[4];
    const float* Wg0   = (const float*)d_in[5];
    const float* bg0   = (const float*)d_in[6];
    const float* tau1  = (const float*)d_in[7];
    const float* Win1  = (const float*)d_in[8];
    const float* Wrec1 = (const float*)d_in[9];
    const float* Wg1   = (const float*)d_in[10];
    const float* bg1   = (const float*)d_in[11];
    const float* W1    = (const float*)d_in[12];
    const float* b1    = (const float*)d_in[13];
    const float* W2    = (const float*)d_in[14];
    const float* b2    = (const float*)d_in[15];
    float* out = (float*)d_out;

    prep_weights<<<(6 * 16384 + 2 * 12288 + 255) / 256, 256>>>(Win0, Wg0, Wrec0,
                                                               Win1, Wrec1, Wg1);
    dim3 g1(S_LEN, B_TOT / 8);
    ltc_precompute<<<g1, 256>>>(seq, ctx, bg0);
    ltc_recurrent<<<128, 256>>>(tau0, tau1, bg1, W1, b1, W2, b2, out);
}

// round 3
// speedup vs baseline: 2.9876x; 1.0743x over previous
#include <cuda_runtime.h>
#include <cstdint>
#include <cstddef>

#define S_LEN 512
#define B_TOT 512

// k-quad-major weight regions: element (j,k) at base + (k>>2)*512 + j*4 + (k&3)
#define OFF_WIN0S 0        // Win0 cols 0..63   (seq part)      16 kq
#define OFF_WG0S  8192     // Wg0  cols 0..63   (seq part)      16 kq
#define OFF_WIN0C 16384    // Win0 cols 64..95  (ctx part)       8 kq
#define OFF_WG0C  20480    // Wg0  cols 64..95  (ctx part)       8 kq
#define OFF_WG0H  24576    // Wg0  cols 96..223 (h part)        32 kq
#define OFF_WREC0 40960    // Wrec0                              32 kq
#define OFF_WIN1  57344    // Win1                               32 kq
#define OFF_WG1X  73728    // Wg1  cols 0..127  (x part)        32 kq
#define OFF_WG1H  90112    // Wg1  cols 128..255(h part)        32 kq
#define OFF_WREC1 106496   // Wrec1                              32 kq
#define W_TOTAL   122880

__device__ __align__(16) float g_W[W_TOTAL];

// ---------------- packed fp32x2 helpers (SASS FFMA2, PTX-only) ----------------
__device__ __forceinline__ unsigned long long ffma2(unsigned long long a,
                                                    unsigned long long b,
                                                    unsigned long long c) {
    unsigned long long d;
    asm("fma.rn.f32x2 %0, %1, %2, %3;" : "=l"(d) : "l"(a), "l"(b), "l"(c));
    return d;
}
__device__ __forceinline__ float redu2(unsigned long long v) {
    float lo, hi;
    asm("mov.b64 {%0, %1}, %2;" : "=f"(lo), "=f"(hi) : "l"(v));
    return lo + hi;
}
__device__ __forceinline__ float sigm(float x) {
    return __fdividef(1.0f, 1.0f + __expf(-x));
}
__device__ __forceinline__ float fast_tanh(float x) {
    float ax = fabsf(x);
    float e = __expf(ax + ax);
    float t = 1.0f - __fdividef(2.0f, e + 1.0f);
    return copysignf(t, x);
}

// ---------------- weight layout prep ----------------
__global__ void __launch_bounds__(256) prep_weights(
    const float* __restrict__ Win0, const float* __restrict__ Wg0,
    const float* __restrict__ Wrec0, const float* __restrict__ Win1,
    const float* __restrict__ Wrec1, const float* __restrict__ Wg1) {
    int idx = blockIdx.x * 256 + threadIdx.x;
    if (idx >= W_TOTAL) return;
    int base;
    if (idx < OFF_WG0S) base = OFF_WIN0S;
    else if (idx < OFF_WIN0C) base = OFF_WG0S;
    else if (idx < OFF_WG0C) base = OFF_WIN0C;
    else if (idx < OFF_WG0H) base = OFF_WG0C;
    else if (idx < OFF_WREC0) base = OFF_WG0H;
    else if (idx < OFF_WIN1) base = OFF_WREC0;
    else if (idx < OFF_WG1X) base = OFF_WIN1;
    else if (idx < OFF_WG1H) base = OFF_WG1X;
    else if (idx < OFF_WREC1) base = OFF_WG1H;
    else base = OFF_WREC1;
    int e = idx - base;
    int j = (e >> 2) & 127;
    int k = ((e >> 9) << 2) | (e & 3);
    float v;
    switch (base) {
        case OFF_WIN0S: v = Win0[j * 96 + k]; break;
        case OFF_WG0S:  v = Wg0[j * 224 + k]; break;
        case OFF_WIN0C: v = Win0[j * 96 + 64 + k]; break;
        case OFF_WG0C:  v = Wg0[j * 224 + 64 + k]; break;
        case OFF_WG0H:  v = Wg0[j * 224 + 96 + k]; break;
        case OFF_WREC0: v = Wrec0[j * 128 + k]; break;
        case OFF_WIN1:  v = Win1[j * 128 + k]; break;
        case OFF_WG1X:  v = Wg1[j * 256 + k]; break;
        case OFF_WG1H:  v = Wg1[j * 256 + 128 + k]; break;
        default:        v = Wrec1[j * 128 + k]; break;
    }
    g_W[idx] = v;
}

// Dual mat-vec: thread computes dot(Wa_row_j, x_b) and dot(Wb_row_j, x_b) for
// b = 0..3. W rows in k-quad layout (warp-coalesced LDG.128); x in smem
// (broadcast LDS.128). KQ = k/4 count, STRIDE = floats between batches.
template <int KQ, int STRIDE>
__device__ __forceinline__ void dualmv(const float* __restrict__ Wa,
                                       const float* __restrict__ Wb,
                                       const float* __restrict__ x,
                                       float ra[4], float rb[4]) {
    unsigned long long a0 = 0, a1 = 0, a2 = 0, a3 = 0;
    unsigned long long c0 = 0, c1 = 0, c2 = 0, c3 = 0;
#pragma unroll 8
    for (int kq = 0; kq < KQ; ++kq) {
        ulonglong2 wa = __ldg(reinterpret_cast<const ulonglong2*>(Wa + (size_t)kq * 512));
        ulonglong2 wb = __ldg(reinterpret_cast<const ulonglong2*>(Wb + (size_t)kq * 512));
        ulonglong2 x0 = *reinterpret_cast<const ulonglong2*>(x + 0 * STRIDE + kq * 4);
        ulonglong2 x1 = *reinterpret_cast<const ulonglong2*>(x + 1 * STRIDE + kq * 4);
        ulonglong2 x2 = *reinterpret_cast<const ulonglong2*>(x + 2 * STRIDE + kq * 4);
        ulonglong2 x3 = *reinterpret_cast<const ulonglong2*>(x + 3 * STRIDE + kq * 4);
        a0 = ffma2(wa.x, x0.x, a0); a0 = ffma2(wa.y, x0.y, a0);
        a1 = ffma2(wa.x, x1.x, a1); a1 = ffma2(wa.y, x1.y, a1);
        a2 = ffma2(wa.x, x2.x, a2); a2 = ffma2(wa.y, x2.y, a2);
        a3 = ffma2(wa.x, x3.x, a3); a3 = ffma2(wa.y, x3.y, a3);
        c0 = ffma2(wb.x, x0.x, c0); c0 = ffma2(wb.y, x0.y, c0);
        c1 = ffma2(wb.x, x1.x, c1); c1 = ffma2(wb.y, x1.y, c1);
        c2 = ffma2(wb.x, x2.x, c2); c2 = ffma2(wb.y, x2.y, c2);
        c3 = ffma2(wb.x, x3.x, c3); c3 = ffma2(wb.y, x3.y, c3);
    }
    ra[0] = redu2(a0); ra[1] = redu2(a1); ra[2] = redu2(a2); ra[3] = redu2(a3);
    rb[0] = redu2(c0); rb[1] = redu2(c1); rb[2] = redu2(c2); rb[3] = redu2(c3);
}

// RK4 for one cell. cu/nx ping-pong smem h buffers (one bar per sub-phase).
// hb: h at cell entry (updated to h_new on exit). If WRITE_H0, the last
// sub-phase writes h0r (cell-0 state) into nx instead of the new h1.
template <bool WRITE_H0>
__device__ __forceinline__ void rk4_cell(const float* __restrict__ Wg,
                                         const float* __restrict__ Wr, float itau,
                                         const float* xin, const float* xg, float* hb,
                                         const float* h0r, float*& cu, float*& nx,
                                         int j) {
    float ka[4] = {0.f, 0.f, 0.f, 0.f};
    float ht[4] = {hb[0], hb[1], hb[2], hb[3]};
#pragma unroll
    for (int sub = 0; sub < 4; ++sub) {
        float ra[4], rb[4];
        dualmv<32, 128>(Wg, Wr, cu, ra, rb);
        const float kw = (sub == 0 || sub == 3) ? 1.0f : 2.0f;
        const float cv = (sub < 2) ? 0.5f : 1.0f;
#pragma unroll
        for (int b = 0; b < 4; ++b) {
            float gate = sigm(fast_tanh(ra[b] + xg[b]));
            float kv = fmaf(gate, rb[b], fmaf(-ht[b], itau, xin[b]));
            ka[b] = fmaf(kw, kv, ka[b]);
            float nh = (sub < 3) ? fmaf(cv, kv, hb[b])
                                 : fast_tanh(fmaf(ka[b], 0.16666667f, hb[b]));
            ht[b] = nh;
            if (sub < 3)
                nx[b * 128 + j] = nh;
            else
                nx[b * 128 + j] = WRITE_H0 ? h0r[b] : nh;
        }
        __syncthreads();
        float* t = cu; cu = nx; nx = t;
    }
    hb[0] = ht[0]; hb[1] = ht[1]; hb[2] = ht[2]; hb[3] = ht[3];
}

// ---------------- persistent recurrence: 128 CTAs x 128 threads ----------------
__global__ void __launch_bounds__(128, 1)
ltc_recurrent(const float* __restrict__ seq, const float* __restrict__ ctx,
              const float* __restrict__ tau0, const float* __restrict__ bg0,
              const float* __restrict__ tau1, const float* __restrict__ bg1,
              const float* __restrict__ W1, const float* __restrict__ b1,
              const float* __restrict__ W2, const float* __restrict__ b2,
              float* __restrict__ out) {
    __shared__ __align__(16) float hhA[4 * 128];
    __shared__ __align__(16) float hhB[4 * 128];
    __shared__ __align__(16) float xx_s[4 * 64];
    const int j = threadIdx.x;
    const int b0g = blockIdx.x * 4;

    const float it0 = __fdividef(1.0f, log1pf(__expf(tau0[j])) + 1.0f);
    const float it1 = __fdividef(1.0f, log1pf(__expf(tau1[j])) + 1.0f);
    const float bg0j = bg0[j];
    const float bg1j = bg1[j];

    const float* Win0s = g_W + OFF_WIN0S + j * 4;
    const float* Wg0s  = g_W + OFF_WG0S  + j * 4;
    const float* Win0c = g_W + OFF_WIN0C + j * 4;
    const float* Wg0c  = g_W + OFF_WG0C  + j * 4;
    const float* Wg0h  = g_W + OFF_WG0H  + j * 4;
    const float* Wrec0 = g_W + OFF_WREC0 + j * 4;
    const float* Win1  = g_W + OFF_WIN1  + j * 4;
    const float* Wg1x  = g_W + OFF_WG1X  + j * 4;
    const float* Wg1h  = g_W + OFF_WG1H  + j * 4;
    const float* Wrec1 = g_W + OFF_WREC1 + j * 4;

    // ---- step-invariant ctx projection: xinc/xgc per batch ----
    {
        int b = j >> 5, i = j & 31;
        xx_s[b * 32 + i] = ctx[(size_t)(b0g + b) * 32 + i];
    }
    __syncthreads();
    float xinc[4], xgc[4];
    dualmv<8, 32>(Win0c, Wg0c, xx_s, xinc, xgc);
#pragma unroll
    for (int b = 0; b < 4; ++b) xgc[b] += bg0j;
    __syncthreads();  // before xx_s reuse

    float h0r[4] = {0.f, 0.f, 0.f, 0.f}, h1r[4] = {0.f, 0.f, 0.f, 0.f};
    float* cu = hhA;
    float* nx = hhB;
#pragma unroll
    for (int b = 0; b < 4; ++b) hhA[b * 128 + j] = 0.f;
    // (covered by the bar at the top of step 0)

    for (int s = 0; s < S_LEN; ++s) {
        // load this step's seq slice: xx_s[b][0..63]
        {
            int b = j >> 5, i2 = j & 31;
            const float2 v = *(reinterpret_cast<const float2*>(
                                   seq + ((size_t)(b0g + b) * S_LEN + s) * 64) + i2);
            *reinterpret_cast<float2*>(xx_s + b * 64 + i2 * 2) = v;
        }
        __syncthreads();

        // cell-0 input projections (seq part) + ctx base
        float xin0[4], xg0[4];
        dualmv<16, 64>(Win0s, Wg0s, xx_s, xin0, xg0);
#pragma unroll
        for (int b = 0; b < 4; ++b) { xin0[b] += xinc[b]; xg0[b] += xgc[b]; }

        // cell 0 (cu holds h0; leaves h0_new in cu and h0r)
        rk4_cell<false>(Wg0h, Wrec0, it0, xin0, xg0, h0r, nullptr, cu, nx, j);

        // cell-1 input projections from h0_new; stage h1 into nx
        float xin1[4], xg1[4];
        dualmv<32, 128>(Win1, Wg1x, cu, xin1, xg1);
#pragma unroll
        for (int b = 0; b < 4; ++b) { xg1[b] += bg1j; nx[b * 128 + j] = h1r[b]; }
        __syncthreads();
        { float* t = cu; cu = nx; nx = t; }

        // cell 1 (last sub writes h0_new back into the buffer for the next step)
        rk4_cell<true>(Wg1h, Wrec1, it1, xin1, xg1, h1r, h0r, cu, nx, j);
    }

    // ---- classifier: sigmoid(relu(h1 @ W1^T + b1) @ W2^T + b2) ----
#pragma unroll
    for (int b = 0; b < 4; ++b) nx[b * 128 + j] = h1r[b];
    __syncthreads();
    const int warp = j >> 5, lane = j & 31;
    {
        const int b = warp;
        float a0 = b1[lane], a1 = b1[lane + 32];
        const float* hv = nx + b * 128;
        const float* w0 = W1 + lane * 128;
        const float* w1 = W1 + (lane + 32) * 128;
#pragma unroll 8
        for (int k = 0; k < 128; ++k) {
            float h = hv[k];
            a0 = fmaf(h, w0[k], a0);
            a1 = fmaf(h, w1[k], a1);
        }
        a0 = fmaxf(a0, 0.f);
        a1 = fmaxf(a1, 0.f);
        float p = a0 * __ldg(W2 + lane) + a1 * __ldg(W2 + lane + 32);
#pragma unroll
        for (int off = 16; off; off >>= 1) p += __shfl_xor_sync(0xffffffffu, p, off);
        if (lane == 0) out[b0g + b] = sigm(p + b2[0]);
    }
}

extern "C" void kernel_launch(void* const* d_in, const int* in_sizes, int n_in,
                              void* d_out, int out_size) {
    const float* seq   = (const float*)d_in[0];
    const float* ctx   = (const float*)d_in[1];
    const float* tau0  = (const float*)d_in[2];
    const float* Win0  = (const float*)d_in[3];
    const float* Wrec0 = (const float*)d_in[4];
    const float* Wg0   = (const float*)d_in[5];
    const float* bg0   = (const float*)d_in[6];
    const float* tau1  = (const float*)d_in[7];
    const float* Win1  = (const float*)d_in[8];
    const float* Wrec1 = (const float*)d_in[9];
    const float* Wg1   = (const float*)d_in[10];
    const float* bg1   = (const float*)d_in[11];
    const float* W1    = (const float*)d_in[12];
    const float* b1    = (const float*)d_in[13];
    const float* W2    = (const float*)d_in[14];
    const float* b2    = (const float*)d_in[15];
    float* out = (float*)d_out;

    prep_weights<<<(W_TOTAL + 255) / 256, 256>>>(Win0, Wg0, Wrec0, Win1, Wrec1, Wg1);
    ltc_recurrent<<<128, 128>>>(seq, ctx, tau0, bg0, tau1, bg1, W1, b1, W2, b2, out);
}

// round 4
// speedup vs baseline: 4.2217x; 1.4131x over previous
#include <cuda_runtime.h>
#include <cstdint>
#include <cstddef>

#define S_LEN 512

// g_W float offsets.
// 64-k split layout  (seq mats):  addr = i*1024 + j*8 + half*4 + e,  k = half*32+i*4+e, i<8
// 128-k split layout (h/x mats):  addr = i*1024 + j*8 + half*4 + e,  k = half*64+i*4+e, i<16
// ctx mats keep old k-quad:       addr = kq*512 + j*4 + e,           k = kq*4+e, kq<8
#define OFF_WIN0S 0
#define OFF_WG0S  8192
#define OFF_WG0H  16384
#define OFF_WREC0 32768
#define OFF_WIN1  49152
#define OFF_WG1X  65536
#define OFF_WG1H  81920
#define OFF_WREC1 98304
#define OFF_WIN0C 114688
#define OFF_WG0C  118784
#define W_TOTAL   122880

__device__ __align__(16) float g_W[W_TOTAL];

// ---------------- packed fp32x2 helpers (SASS FFMA2, PTX-only) ----------------
__device__ __forceinline__ unsigned long long ffma2(unsigned long long a,
                                                    unsigned long long b,
                                                    unsigned long long c) {
    unsigned long long d;
    asm("fma.rn.f32x2 %0, %1, %2, %3;" : "=l"(d) : "l"(a), "l"(b), "l"(c));
    return d;
}
__device__ __forceinline__ float redu2(unsigned long long v) {
    float lo, hi;
    asm("mov.b64 {%0, %1}, %2;" : "=f"(lo), "=f"(hi) : "l"(v));
    return lo + hi;
}
__device__ __forceinline__ float sigm(float x) {
    return __fdividef(1.0f, 1.0f + __expf(-x));
}
__device__ __forceinline__ float fast_tanh(float x) {
    float ax = fabsf(x);
    float e = __expf(ax + ax);
    float t = 1.0f - __fdividef(2.0f, e + 1.0f);
    return copysignf(t, x);
}
// reduce packed acc + combine the two k-halves across lanes l and l^16
__device__ __forceinline__ float redsum(unsigned long long v) {
    float r = redu2(v);
    r += __shfl_xor_sync(0xffffffffu, r, 16);
    return r;
}

// ---------------- weight layout prep ----------------
__global__ void __launch_bounds__(256) prep_weights(
    const float* __restrict__ Win0, const float* __restrict__ Wg0,
    const float* __restrict__ Wrec0, const float* __restrict__ Win1,
    const float* __restrict__ Wrec1, const float* __restrict__ Wg1) {
    int idx = blockIdx.x * 256 + threadIdx.x;
    if (idx >= W_TOTAL) return;
    float v;
    if (idx < 16384) {  // 64-k split: Win0 seq-part / Wg0 seq-part
        int m = idx >> 13;
        int r = idx & 8191;
        int i = r >> 10, j = (r >> 3) & 127, hf = (r >> 2) & 1, e = r & 3;
        int k = hf * 32 + i * 4 + e;
        v = m ? Wg0[j * 224 + k] : Win0[j * 96 + k];
    } else if (idx < 114688) {  // 128-k split mats
        int m = (idx - 16384) >> 14;
        int r = (idx - 16384) & 16383;
        int i = r >> 10, j = (r >> 3) & 127, hf = (r >> 2) & 1, e = r & 3;
        int k = hf * 64 + i * 4 + e;
        switch (m) {
            case 0: v = Wg0[j * 224 + 96 + k]; break;
            case 1: v = Wrec0[j * 128 + k]; break;
            case 2: v = Win1[j * 128 + k]; break;
            case 3: v = Wg1[j * 256 + k]; break;
            case 4: v = Wg1[j * 256 + 128 + k]; break;
            default: v = Wrec1[j * 128 + k]; break;
        }
    } else {  // ctx parts, old k-quad layout
        int m = (idx - 114688) >> 12;
        int r = (idx - 114688) & 4095;
        int j = (r >> 2) & 127;
        int k = ((r >> 9) << 2) | (r & 3);
        v = m ? Wg0[j * 224 + 64 + k] : Win0[j * 96 + 64 + k];
    }
    g_W[idx] = v;
}

// Split-k dual mat-vec. This thread covers row jl, k-half `half` (already folded
// into the W pointers and xoff). ITERS = (k/2)/4. x is in the interleaved smem
// layout (slot = i*8 + half*4 + e). Results combined across halves via shfl.
template <int ITERS, int XSTRIDE>
__device__ __forceinline__ void dualmv_sp(const float* __restrict__ Wa,
                                          const float* __restrict__ Wb,
                                          const float* __restrict__ x, int xoff,
                                          float ra[4], float rb[4]) {
    unsigned long long a[4] = {0, 0, 0, 0};
    unsigned long long c[4] = {0, 0, 0, 0};
#pragma unroll
    for (int i = 0; i < ITERS; ++i) {
        ulonglong2 wa = __ldg(reinterpret_cast<const ulonglong2*>(Wa + (size_t)i * 1024));
        ulonglong2 wb = __ldg(reinterpret_cast<const ulonglong2*>(Wb + (size_t)i * 1024));
#pragma unroll
        for (int b = 0; b < 4; ++b) {
            ulonglong2 xv =
                *reinterpret_cast<const ulonglong2*>(x + b * XSTRIDE + i * 8 + xoff);
            a[b] = ffma2(wa.x, xv.x, a[b]);
            a[b] = ffma2(wa.y, xv.y, a[b]);
            c[b] = ffma2(wb.x, xv.x, c[b]);
            c[b] = ffma2(wb.y, xv.y, c[b]);
        }
    }
#pragma unroll
    for (int b = 0; b < 4; ++b) {
        ra[b] = redsum(a[b]);
        rb[b] = redsum(c[b]);
    }
}

// RK4 for one cell; cu/nx ping-pong interleaved h buffers (1 bar per sub-phase).
// Only half==0 threads store (each row owned by exactly one such thread).
template <bool WRITE_H0>
__device__ __forceinline__ void rk4_cell(const float* __restrict__ Wg,
                                         const float* __restrict__ Wr, float itau,
                                         const float* xin, const float* xg, float* hb,
                                         const float* h0r, float*& cu, float*& nx,
                                         int xoff, int hslot, int half) {
    float ka[4] = {0.f, 0.f, 0.f, 0.f};
    float ht[4] = {hb[0], hb[1], hb[2], hb[3]};
#pragma unroll
    for (int sub = 0; sub < 4; ++sub) {
        float ra[4], rb[4];
        dualmv_sp<16, 128>(Wg, Wr, cu, xoff, ra, rb);
        const float kw = (sub == 0 || sub == 3) ? 1.0f : 2.0f;
        const float cv = (sub < 2) ? 0.5f : 1.0f;
#pragma unroll
        for (int b = 0; b < 4; ++b) {
            float gate = sigm(fast_tanh(ra[b] + xg[b]));
            float kv = fmaf(gate, rb[b], fmaf(-ht[b], itau, xin[b]));
            ka[b] = fmaf(kw, kv, ka[b]);
            float nh = (sub < 3) ? fmaf(cv, kv, hb[b])
                                 : fast_tanh(fmaf(ka[b], 0.16666667f, hb[b]));
            ht[b] = nh;
            if (half == 0)
                nx[b * 128 + hslot] = (sub == 3 && WRITE_H0) ? h0r[b] : nh;
        }
        __syncthreads();
        float* t = cu; cu = nx; nx = t;
    }
    hb[0] = ht[0]; hb[1] = ht[1]; hb[2] = ht[2]; hb[3] = ht[3];
}

// ---------------- persistent recurrence: 128 CTAs x 256 threads ----------------
// Warp w covers rows jl = w*16 + (lane&15); lane half = lane>>4 covers one k-half.
__global__ void __launch_bounds__(256, 1)
ltc_recurrent(const float* __restrict__ seq, const float* __restrict__ ctx,
              const float* __restrict__ tau0, const float* __restrict__ bg0,
              const float* __restrict__ tau1, const float* __restrict__ bg1,
              const float* __restrict__ W1, const float* __restrict__ b1,
              const float* __restrict__ W2, const float* __restrict__ b2,
              float* __restrict__ out) {
    __shared__ __align__(16) float hhA[4 * 128];
    __shared__ __align__(16) float hhB[4 * 128];
    __shared__ __align__(16) float xs[4 * 64];   // per-step seq x (interleaved, 8-iter)
    __shared__ __align__(16) float xc[4 * 32];   // ctx (plain)
    __shared__ __align__(16) float st0[4 * 128]; // staging: ctx proj xin / final h1
    __shared__ __align__(16) float st1[4 * 128]; // staging: ctx proj xg
    const int tid = threadIdx.x;
    const int lane = tid & 31;
    const int w = tid >> 5;
    const int half = lane >> 4;
    const int jl = (w << 4) + (lane & 15);
    const int xoff = half * 4;
    const int hslot = ((jl >> 2) & 15) * 8 + (jl >> 6) * 4 + (jl & 3);
    const int b0g = blockIdx.x * 4;

    const float it0 = __fdividef(1.0f, log1pf(__expf(tau0[jl])) + 1.0f);
    const float it1 = __fdividef(1.0f, log1pf(__expf(tau1[jl])) + 1.0f);
    const float bg1j = bg1[jl];

    const int wo = jl * 8 + half * 4;
    const float* Win0s = g_W + OFF_WIN0S + wo;
    const float* Wg0s  = g_W + OFF_WG0S  + wo;
    const float* Wg0h  = g_W + OFF_WG0H  + wo;
    const float* Wrec0 = g_W + OFF_WREC0 + wo;
    const float* Win1  = g_W + OFF_WIN1  + wo;
    const float* Wg1x  = g_W + OFF_WG1X  + wo;
    const float* Wg1h  = g_W + OFF_WG1H  + wo;
    const float* Wrec1 = g_W + OFF_WREC1 + wo;

    // ---- step-invariant ctx projection (old layout, threads 0-127) ----
    if (tid < 128) {
        int b = tid >> 5, i = tid & 31;
        xc[b * 32 + i] = ctx[(size_t)(b0g + b) * 32 + i];
    }
    __syncthreads();
    if (tid < 128) {
        const int j = tid;
        const float* Wa = g_W + OFF_WIN0C + j * 4;
        const float* Wb = g_W + OFF_WG0C + j * 4;
        unsigned long long a[4] = {0, 0, 0, 0}, c[4] = {0, 0, 0, 0};
#pragma unroll
        for (int kq = 0; kq < 8; ++kq) {
            ulonglong2 wa = __ldg(reinterpret_cast<const ulonglong2*>(Wa + kq * 512));
            ulonglong2 wb = __ldg(reinterpret_cast<const ulonglong2*>(Wb + kq * 512));
#pragma unroll
            for (int b = 0; b < 4; ++b) {
                ulonglong2 xv = *reinterpret_cast<const ulonglong2*>(xc + b * 32 + kq * 4);
                a[b] = ffma2(wa.x, xv.x, a[b]);
                a[b] = ffma2(wa.y, xv.y, a[b]);
                c[b] = ffma2(wb.x, xv.x, c[b]);
                c[b] = ffma2(wb.y, xv.y, c[b]);
            }
        }
        const float bg0j = bg0[j];
#pragma unroll
        for (int b = 0; b < 4; ++b) {
            st0[b * 128 + j] = redu2(a[b]);
            st1[b * 128 + j] = redu2(c[b]) + bg0j;
        }
    }
    __syncthreads();
    float xinc[4], xgc[4];
#pragma unroll
    for (int b = 0; b < 4; ++b) {
        xinc[b] = st0[b * 128 + jl];
        xgc[b] = st1[b * 128 + jl];
    }

    float h0r[4] = {0.f, 0.f, 0.f, 0.f}, h1r[4] = {0.f, 0.f, 0.f, 0.f};
    float* cu = hhA;
    float* nx = hhB;
    hhA[tid] = 0.f;
    hhA[256 + tid] = 0.f;

    for (int s = 0; s < S_LEN; ++s) {
        // load this step's seq slice into interleaved xs
        {
            int b = tid >> 6, k = tid & 63;
            float v = seq[((size_t)(b0g + b) * S_LEN + s) * 64 + k];
            int sl = ((k >> 2) & 7) * 8 + (k >> 5) * 4 + (k & 3);
            xs[b * 64 + sl] = v;
        }
        __syncthreads();

        // cell-0 input projections (seq part) + ctx base
        float xin0[4], xg0[4];
        dualmv_sp<8, 64>(Win0s, Wg0s, xs, xoff, xin0, xg0);
#pragma unroll
        for (int b = 0; b < 4; ++b) { xin0[b] += xinc[b]; xg0[b] += xgc[b]; }

        // cell 0 (cu holds h0 interleaved; leaves h0_new in cu and h0r)
        rk4_cell<false>(Wg0h, Wrec0, it0, xin0, xg0, h0r, nullptr, cu, nx, xoff,
                        hslot, half);

        // cell-1 input projections from h0_new; stage h1 into nx
        float xin1[4], xg1[4];
        dualmv_sp<16, 128>(Win1, Wg1x, cu, xoff, xin1, xg1);
#pragma unroll
        for (int b = 0; b < 4; ++b) {
            xg1[b] += bg1j;
            if (half == 0) nx[b * 128 + hslot] = h1r[b];
        }
        __syncthreads();
        { float* t = cu; cu = nx; nx = t; }

        // cell 1 (last sub writes h0_new back for the next step's cell 0)
        rk4_cell<true>(Wg1h, Wrec1, it1, xin1, xg1, h1r, h0r, cu, nx, xoff,
                       hslot, half);
    }

    // ---- classifier: sigmoid(relu(h1 @ W1^T + b1) @ W2^T + b2) ----
    __syncthreads();
    if (half == 0) {
#pragma unroll
        for (int b = 0; b < 4; ++b) st0[b * 128 + jl] = h1r[b];
    }
    __syncthreads();
    if (tid < 128) {
        const int warp = tid >> 5, ln = tid & 31;
        const int b = warp;
        float a0 = b1[ln], a1 = b1[ln + 32];
        const float* hv = st0 + b * 128;
        const float* w0 = W1 + ln * 128;
        const float* w1 = W1 + (ln + 32) * 128;
#pragma unroll 8
        for (int k = 0; k < 128; ++k) {
            float h = hv[k];
            a0 = fmaf(h, w0[k], a0);
            a1 = fmaf(h, w1[k], a1);
        }
        a0 = fmaxf(a0, 0.f);
        a1 = fmaxf(a1, 0.f);
        float p = a0 * __ldg(W2 + ln) + a1 * __ldg(W2 + ln + 32);
#pragma unroll
        for (int off = 16; off; off >>= 1) p += __shfl_xor_sync(0xffffffffu, p, off);
        if (ln == 0) out[b0g + b] = sigm(p + b2[0]);
    }
}

extern "C" void kernel_launch(void* const* d_in, const int* in_sizes, int n_in,
                              void* d_out, int out_size) {
    const float* seq   = (const float*)d_in[0];
    const float* ctx   = (const float*)d_in[1];
    const float* tau0  = (const float*)d_in[2];
    const float* Win0  = (const float*)d_in[3];
    const float* Wrec0 = (const float*)d_in[4];
    const float* Wg0   = (const float*)d_in[5];
    const float* bg0   = (const float*)d_in[6];
    const float* tau1  = (const float*)d_in[7];
    const float* Win1  = (const float*)d_in[8];
    const float* Wrec1 = (const float*)d_in[9];
    const float* Wg1   = (const float*)d_in[10];
    const float* bg1   = (const float*)d_in[11];
    const float* W1    = (const float*)d_in[12];
    const float* b1    = (const float*)d_in[13];
    const float* W2    = (const float*)d_in[14];
    const float* b2    = (const float*)d_in[15];
    float* out = (float*)d_out;

    prep_weights<<<(W_TOTAL + 255) / 256, 256>>>(Win0, Wg0, Wrec0, Win1, Wrec1, Wg1);
    ltc_recurrent<<<128, 256>>>(seq, ctx, tau0, bg0, tau1, bg1, W1, b1, W2, b2, out);
}